// round 1
// baseline (speedup 1.0000x reference)
#include <cuda_runtime.h>
#include <cuda_bf16.h>
#include <math.h>

// Problem dims
#define NROWS 65536
#define SSTR  128
#define DINV  512
#define HID   1024
#define DOUTV 256

// GEMM tile config for mlp_reduce
#define BM 128
#define BH 128
#define BK 8

// ---------------- scratch (device globals; no allocation) ----------------
__device__ float g_v[HID];            // W2 @ w_deep
__device__ float g_c;                 // b2 . w_deep
__device__ float g_y[NROWS];          // Uhat @ w_deep
__device__ float g_Gpart[128 * SSTR * SSTR];  // per-block Gram partials (8.4 MB)
__device__ float g_rpart[128 * SSTR];         // per-block A^T y partials
__device__ float g_G[SSTR * SSTR];
__device__ float g_r[SSTR];
__device__ float g_wz[SSTR];          // w_struct - z

// ---------------- kernel A: v = W2 @ w_deep, c = b2 . w_deep ----------------
__global__ void head_kernel(const float* __restrict__ W2,
                            const float* __restrict__ b2,
                            const float* __restrict__ w_deep) {
    int h = blockIdx.x * blockDim.x + threadIdx.x;
    if (h < HID) {
        const float* wrow = W2 + (size_t)h * DOUTV;
        float s = 0.f;
        #pragma unroll 4
        for (int d = 0; d < DOUTV; d++) s = fmaf(wrow[d], __ldg(&w_deep[d]), s);
        g_v[h] = s;
    }
    if (h == 0) {
        float c = 0.f;
        for (int d = 0; d < DOUTV; d++) c = fmaf(b2[d], w_deep[d], c);
        g_c = c;
    }
}

// ---------------- kernel B: y[n] = c + sum_h relu(d1@W1 + b1)[n,h] * v[h] ----------------
// Classic 128x128x8 register-tiled fp32 GEMM, 256 threads, 8x8 micro-tile,
// with the N(=H) dimension fully reduced through relu*v in the epilogue.
__global__ __launch_bounds__(256) void mlp_reduce(const float* __restrict__ d1,
                                                  const float* __restrict__ W1,
                                                  const float* __restrict__ b1) {
    __shared__ float As[BK][BM];     // transposed A tile: [k][m]
    __shared__ float Bs[BK][BH];     // [k][h]
    __shared__ float red[BM][17];    // padded for conflict-free reduce

    const int tid = threadIdx.x;
    const int tx = tid & 15;         // h direction (16)
    const int ty = tid >> 4;         // m direction (16)
    const int row0 = blockIdx.x * BM;

    // loader lanes
    const int ar  = tid >> 1;          // 0..127: row in tile
    const int akq = (tid & 1) * 4;     // k offset {0,4}
    const int bk  = tid >> 5;          // 0..7
    const int bh4 = (tid & 31) * 4;    // 0..124

    float yacc[8];
    #pragma unroll
    for (int i = 0; i < 8; i++) yacc[i] = 0.f;

    for (int ht = 0; ht < HID / BH; ht++) {
        float acc[8][8];
        #pragma unroll
        for (int i = 0; i < 8; i++)
            #pragma unroll
            for (int j = 0; j < 8; j++) acc[i][j] = 0.f;

        for (int kt = 0; kt < DINV / BK; kt++) {
            float4 av = *reinterpret_cast<const float4*>(
                &d1[(size_t)(row0 + ar) * DINV + kt * BK + akq]);
            float4 bv = *reinterpret_cast<const float4*>(
                &W1[(size_t)(kt * BK + bk) * HID + ht * BH + bh4]);
            __syncthreads();   // previous iteration's reads complete
            As[akq + 0][ar] = av.x;
            As[akq + 1][ar] = av.y;
            As[akq + 2][ar] = av.z;
            As[akq + 3][ar] = av.w;
            *reinterpret_cast<float4*>(&Bs[bk][bh4]) = bv;
            __syncthreads();
            #pragma unroll
            for (int kk = 0; kk < BK; kk++) {
                float a[8], b[8];
                #pragma unroll
                for (int i = 0; i < 8; i++) a[i] = As[kk][ty * 8 + i];
                #pragma unroll
                for (int j = 0; j < 8; j++) b[j] = Bs[kk][tx * 8 + j];
                #pragma unroll
                for (int i = 0; i < 8; i++)
                    #pragma unroll
                    for (int j = 0; j < 8; j++)
                        acc[i][j] = fmaf(a[i], b[j], acc[i][j]);
            }
        }
        // epilogue: relu + weighted reduce over this h-tile
        #pragma unroll
        for (int j = 0; j < 8; j++) {
            int h = ht * BH + tx * 8 + j;
            float vh = g_v[h];
            float bh = __ldg(&b1[h]);
            #pragma unroll
            for (int i = 0; i < 8; i++) {
                float t = acc[i][j] + bh;
                t = t > 0.f ? t : 0.f;
                yacc[i] = fmaf(t, vh, yacc[i]);
            }
        }
    }

    // cross-thread (tx) reduction per row
    __syncthreads();
    #pragma unroll
    for (int i = 0; i < 8; i++) red[ty * 8 + i][tx] = yacc[i];
    __syncthreads();
    if (tid < BM) {
        float s = 0.f;
        #pragma unroll
        for (int t = 0; t < 16; t++) s += red[tid][t];
        g_y[row0 + tid] = s + g_c;
    }
}

// ---------------- kernel C: per-block partials of G = A^T A and r = A^T y ----------------
// 128 blocks x 256 threads, 512 rows per block. No atomics (determinism).
__global__ __launch_bounds__(256) void gram_partial(const float* __restrict__ A) {
    __shared__ float rowS[SSTR];
    __shared__ float yS;
    const int tid = threadIdx.x;
    const int i  = tid >> 1;          // 0..127
    const int jb = (tid & 1) * 64;    // 0 or 64
    float acc[64];
    #pragma unroll
    for (int jj = 0; jj < 64; jj++) acc[jj] = 0.f;
    float racc = 0.f;

    const int n0 = blockIdx.x * (NROWS / 128);
    for (int n = n0; n < n0 + NROWS / 128; n++) {
        __syncthreads();
        if (tid < SSTR) rowS[tid] = A[(size_t)n * SSTR + tid];
        if (tid == SSTR) yS = g_y[n];
        __syncthreads();
        float ai = rowS[i];
        #pragma unroll
        for (int jj = 0; jj < 64; jj++)
            acc[jj] = fmaf(ai, rowS[jb + jj], acc[jj]);
        if (tid < SSTR) racc = fmaf(rowS[tid], yS, racc);
    }
    float* gp = &g_Gpart[(size_t)blockIdx.x * SSTR * SSTR + i * SSTR + jb];
    #pragma unroll
    for (int jj = 0; jj < 64; jj++) gp[jj] = acc[jj];
    if (tid < SSTR) g_rpart[(size_t)blockIdx.x * SSTR + tid] = racc;
}

__global__ void gram_reduce() {
    int idx = blockIdx.x * blockDim.x + threadIdx.x;
    if (idx < SSTR * SSTR) {
        float s = 0.f;
        #pragma unroll 8
        for (int b = 0; b < 128; b++) s += g_Gpart[(size_t)b * SSTR * SSTR + idx];
        g_G[idx] = s;
    }
    if (idx < SSTR) {
        float s = 0.f;
        #pragma unroll 8
        for (int b = 0; b < 128; b++) s += g_rpart[(size_t)b * SSTR + idx];
        g_r[idx] = s;
    }
}

// ---------------- kernel D: Cholesky solve G z = r; wz = w_struct - z ----------------
// Single block, 128 threads. Lower triangle packed in 33KB static smem.
__global__ __launch_bounds__(128) void solve_kernel(const float* __restrict__ w_struct) {
    __shared__ float T[SSTR * (SSTR + 1) / 2];   // packed lower triangle
    __shared__ float rv[SSTR], wv[SSTR], zv[SSTR];
    const int tid = threadIdx.x;
    const int myb = tid * (tid + 1) / 2;

    // load row tid of lower triangle
    for (int j = 0; j <= tid; j++) T[myb + j] = g_G[tid * SSTR + j];
    rv[tid] = g_r[tid];
    __syncthreads();

    // Cholesky (right-looking)
    for (int k = 0; k < SSTR; k++) {
        const int kb = k * (k + 1) / 2;
        float dk = T[kb + k];
        float s = sqrtf(dk);
        float inv = 1.0f / s;
        __syncthreads();               // all read dk before any write
        if (tid == k) T[kb + k] = s;
        float lik = 0.f;
        if (tid > k) { lik = T[myb + k] * inv; T[myb + k] = lik; }
        __syncthreads();
        if (tid > k) {
            int jb_ = (k + 1) * (k + 2) / 2;   // base of row j=k+1
            for (int j = k + 1; j <= tid; j++) {
                T[myb + j] -= lik * T[jb_ + k];  // T[jb_+k] broadcast across lanes
                jb_ += j + 1;
            }
        }
        __syncthreads();
    }

    // forward: L w = r
    for (int k = 0; k < SSTR; k++) {
        const int kb = k * (k + 1) / 2;
        if (tid == k) wv[k] = rv[k] / T[kb + k];
        __syncthreads();
        if (tid > k) rv[tid] -= T[myb + k] * wv[k];
        __syncthreads();
    }
    // backward: L^T z = w
    for (int k = SSTR - 1; k >= 0; k--) {
        const int kb = k * (k + 1) / 2;
        if (tid == k) zv[k] = wv[k] / T[kb + k];
        __syncthreads();
        if (tid < k) wv[tid] -= T[kb + tid] * zv[k];
        __syncthreads();
    }
    g_wz[tid] = w_struct[tid] - zv[tid];
}

// ---------------- kernel E: out[n] = y[n] + A[n,:] . wz ----------------
__global__ __launch_bounds__(256) void final_kernel(const float* __restrict__ A,
                                                    float* __restrict__ out) {
    int warp = (blockIdx.x * blockDim.x + threadIdx.x) >> 5;
    int lane = threadIdx.x & 31;
    if (warp >= NROWS) return;
    const float* row = A + (size_t)warp * SSTR;
    float s = 0.f;
    #pragma unroll
    for (int q = 0; q < 4; q++) {
        int sidx = q * 32 + lane;
        s = fmaf(row[sidx], g_wz[sidx], s);
    }
    #pragma unroll
    for (int off = 16; off; off >>= 1) s += __shfl_xor_sync(0xffffffffu, s, off);
    if (lane == 0) out[warp] = g_y[warp] + s;
}

// ---------------- launch ----------------
extern "C" void kernel_launch(void* const* d_in, const int* in_sizes, int n_in,
                              void* d_out, int out_size) {
    const float* structured = (const float*)d_in[0];   // [N, S]
    const float* d1         = (const float*)d_in[1];   // [N, DIN]
    const float* W1         = (const float*)d_in[2];   // [DIN, H]
    const float* b1         = (const float*)d_in[3];   // [H]
    const float* W2         = (const float*)d_in[4];   // [H, DOUT]
    const float* b2         = (const float*)d_in[5];   // [DOUT]
    const float* w_struct   = (const float*)d_in[6];   // [S, 1]
    const float* w_deep     = (const float*)d_in[7];   // [DOUT, 1]
    float* out = (float*)d_out;                        // [N, 1]

    head_kernel<<<(HID + 255) / 256, 256>>>(W2, b2, w_deep);
    mlp_reduce<<<NROWS / BM, 256>>>(d1, W1, b1);
    gram_partial<<<128, 256>>>(structured);
    gram_reduce<<<(SSTR * SSTR + 255) / 256, 256>>>();
    solve_kernel<<<1, 128>>>(w_struct);
    final_kernel<<<(NROWS * 32) / 256, 256>>>(structured, out);
}

// round 6
// speedup vs baseline: 2.5170x; 2.5170x over previous
#include <cuda_runtime.h>
#include <cuda_fp16.h>
#include <math.h>
#include <stdint.h>

// Problem dims
#define NROWS 65536
#define SSTR  128
#define DINV  512
#define HID   1024
#define DOUTV 256

// ---------------- scratch (device globals; no allocation) ----------------
__device__ float g_v[HID];            // W2 @ w_deep
__device__ float g_c;                 // b2 . w_deep
__device__ float g_y[NROWS];          // Uhat @ w_deep
__device__ float g_Gpart[128 * SSTR * SSTR];
__device__ float g_rpart[128 * SSTR];
__device__ float g_G[SSTR * SSTR];
__device__ float g_r[SSTR];
__device__ float g_wz[SSTR];

// fp16 copies
__device__ __half g_d1h[(size_t)NROWS * DINV];   // [N][K]
__device__ __half g_W1h[(size_t)DINV * HID];     // [K][H] (row-major, same as W1)

// ---------------- PTX helpers ----------------
__device__ __forceinline__ uint32_t smem_u32(const void* p) {
    uint32_t a;
    asm("{ .reg .u64 t; cvta.to.shared.u64 t, %1; cvt.u32.u64 %0, t; }"
        : "=r"(a) : "l"(p));
    return a;
}
__device__ __forceinline__ void cp16(uint32_t dst, const void* src) {
    asm volatile("cp.async.cg.shared.global [%0], [%1], 16;" :: "r"(dst), "l"(src));
}
__device__ __forceinline__ void ldsm4(uint32_t r[4], uint32_t addr) {
    asm volatile("ldmatrix.sync.aligned.m8n8.x4.shared.b16 {%0,%1,%2,%3}, [%4];"
        : "=r"(r[0]), "=r"(r[1]), "=r"(r[2]), "=r"(r[3]) : "r"(addr));
}
__device__ __forceinline__ void ldsm4t(uint32_t r[4], uint32_t addr) {
    asm volatile("ldmatrix.sync.aligned.m8n8.x4.trans.shared.b16 {%0,%1,%2,%3}, [%4];"
        : "=r"(r[0]), "=r"(r[1]), "=r"(r[2]), "=r"(r[3]) : "r"(addr));
}
__device__ __forceinline__ void mma16816(float c[4], const uint32_t a[4],
                                         uint32_t b0, uint32_t b1) {
    asm volatile(
        "mma.sync.aligned.m16n8k16.row.col.f32.f16.f16.f32 "
        "{%0,%1,%2,%3}, {%4,%5,%6,%7}, {%8,%9}, {%0,%1,%2,%3};"
        : "+f"(c[0]), "+f"(c[1]), "+f"(c[2]), "+f"(c[3])
        : "r"(a[0]), "r"(a[1]), "r"(a[2]), "r"(a[3]), "r"(b0), "r"(b1));
}

// smem layout (dynamic)
#define SB_A     0u                     // A resident: 128 x 512 fp16 = 131072
#define SB_B     131072u                // B double-buffered: 2 x (64 x 256 fp16 = 32768)
#define SB_BV    196608u                // bvS[1024] fp32
#define SB_V     200704u                // vS[1024] fp32
#define SB_RED   204800u                // red[128][4] fp32 = 2048
#define SMEM_TOTAL 206848u

// ---------------- kernel A: v = W2 @ w_deep, c = b2 . w_deep ----------------
__global__ void head_kernel(const float* __restrict__ W2,
                            const float* __restrict__ b2,
                            const float* __restrict__ w_deep) {
    int h = blockIdx.x * blockDim.x + threadIdx.x;
    if (h < HID) {
        const float* wrow = W2 + (size_t)h * DOUTV;
        float s = 0.f;
        #pragma unroll 4
        for (int d = 0; d < DOUTV; d++) s = fmaf(wrow[d], __ldg(&w_deep[d]), s);
        g_v[h] = s;
    }
    if (h == 0) {
        float c = 0.f;
        for (int d = 0; d < DOUTV; d++) c = fmaf(b2[d], w_deep[d], c);
        g_c = c;
    }
}

// ---------------- conversions to fp16 ----------------
__global__ __launch_bounds__(256) void conv_d1h(const float* __restrict__ d1) {
    size_t i = (size_t)blockIdx.x * 256 + threadIdx.x;   // float4 index
    float4 f = reinterpret_cast<const float4*>(d1)[i];
    __half2 a = __floats2half2_rn(f.x, f.y);
    __half2 b = __floats2half2_rn(f.z, f.w);
    reinterpret_cast<__half2*>(g_d1h)[2 * i]     = a;
    reinterpret_cast<__half2*>(g_d1h)[2 * i + 1] = b;
}
__global__ __launch_bounds__(256) void conv_W1h(const float* __restrict__ W1) {
    size_t i = (size_t)blockIdx.x * 256 + threadIdx.x;
    float4 f = reinterpret_cast<const float4*>(W1)[i];
    __half2 a = __floats2half2_rn(f.x, f.y);
    __half2 b = __floats2half2_rn(f.z, f.w);
    reinterpret_cast<__half2*>(g_W1h)[2 * i]     = a;
    reinterpret_cast<__half2*>(g_W1h)[2 * i + 1] = b;
}

// ---------------- tensor-core MLP reduce (mma.sync fp16) ----------------
// CTA: 256 threads = 8 warps (wm in {0,1} x wn in {0..3}); warp tile 64x64.
// CTA tile: M=128 rows (A resident, K=512), N=256 cols per h-tile, 4 h-tiles.
__device__ __forceinline__ void loadB_chunk(int s, uint32_t sbB, int tid) {
    int ht = s >> 3, kc = s & 7;
    uint32_t base = sbB + (uint32_t)(s & 1) * 32768u;
    #pragma unroll
    for (int i = 0; i < 8; i++) {
        int c = tid + i * 256;
        int kr = c >> 5, p = c & 31;
        uint32_t dst = base + kr * 512 + ((uint32_t)(p ^ (kr & 7)) << 4);
        cp16(dst, g_W1h + (size_t)(kc * 64 + kr) * HID + ht * 256 + p * 8);
    }
}

__global__ void __launch_bounds__(256, 1) mlp_tc(const float* __restrict__ b1) {
    extern __shared__ char smem[];
    const uint32_t sb = smem_u32(smem);
    const uint32_t sbA = sb + SB_A;
    const uint32_t sbB = sb + SB_B;
    float* bvS = (float*)(smem + SB_BV);
    float* vS  = (float*)(smem + SB_V);
    float* red = (float*)(smem + SB_RED);

    const int tid = threadIdx.x;
    const int lane = tid & 31;
    const int wid = tid >> 5;
    const int wm = wid & 1;       // M half (64 rows)
    const int wn = wid >> 1;      // N quarter (64 cols)
    const int row0 = blockIdx.x * 128;

    // prologue: A resident load + B chunk 0 + bias/v vectors
    #pragma unroll
    for (int i = 0; i < 32; i++) {
        int c = tid + i * 256;
        int r = c >> 6, p = c & 63;
        uint32_t dst = sbA + r * 1024 + ((uint32_t)(p ^ (r & 7)) << 4);
        cp16(dst, g_d1h + (size_t)(row0 + r) * DINV + p * 8);
    }
    loadB_chunk(0, sbB, tid);
    asm volatile("cp.async.commit_group;" ::: "memory");
    for (int i = tid; i < HID; i += 256) {
        bvS[i] = __ldg(&b1[i]);
        vS[i]  = g_v[i];
    }

    float acc[4][8][4];
    #pragma unroll
    for (int mt = 0; mt < 4; mt++)
        #pragma unroll
        for (int nt = 0; nt < 8; nt++)
            #pragma unroll
            for (int q = 0; q < 4; q++) acc[mt][nt][q] = 0.f;
    float yacc[8];
    #pragma unroll
    for (int i = 0; i < 8; i++) yacc[i] = 0.f;

    for (int s = 0; s < 32; s++) {
        if (s + 1 < 32) {
            loadB_chunk(s + 1, sbB, tid);
            asm volatile("cp.async.commit_group;" ::: "memory");
            asm volatile("cp.async.wait_group 1;" ::: "memory");
        } else {
            asm volatile("cp.async.wait_group 0;" ::: "memory");
        }
        __syncthreads();

        const uint32_t bb = sbB + (uint32_t)(s & 1) * 32768u;
        #pragma unroll
        for (int k16 = 0; k16 < 4; k16++) {
            uint32_t af[4][4], bf[4][4];
            #pragma unroll
            for (int mt = 0; mt < 4; mt++) {
                int r = wm * 64 + mt * 16 + (lane & 15);
                int kch = (s & 7) * 8 + k16 * 2 + (lane >> 4);
                ldsm4(af[mt], sbA + r * 1024 + ((uint32_t)(kch ^ (r & 7)) << 4));
            }
            #pragma unroll
            for (int np = 0; np < 4; np++) {
                int m = lane >> 3;
                int kr = k16 * 16 + ((m & 1) << 3) + (lane & 7);
                int nch = wn * 8 + np * 2 + (m >> 1);
                ldsm4t(bf[np], bb + kr * 512 + ((uint32_t)(nch ^ (kr & 7)) << 4));
            }
            #pragma unroll
            for (int mt = 0; mt < 4; mt++)
                #pragma unroll
                for (int nt = 0; nt < 8; nt++) {
                    int np = nt >> 1, od = nt & 1;
                    mma16816(acc[mt][nt], af[mt], bf[np][od * 2], bf[np][od * 2 + 1]);
                }
        }

        if ((s & 7) == 7) {
            // epilogue for h-tile ht = s>>3: relu(acc + b1) * v -> row partials
            int ht = s >> 3;
            #pragma unroll
            for (int mt = 0; mt < 4; mt++)
                #pragma unroll
                for (int nt = 0; nt < 8; nt++) {
                    int np = nt >> 1, od = nt & 1;
                    int col = ht * 256 + wn * 64 + np * 16 + od * 8 + (lane & 3) * 2;
                    float b0 = bvS[col], b1v = bvS[col + 1];
                    float v0 = vS[col], v1 = vS[col + 1];
                    float x;
                    x = fmaxf(acc[mt][nt][0] + b0, 0.f);  yacc[mt * 2]     = fmaf(x, v0, yacc[mt * 2]);
                    x = fmaxf(acc[mt][nt][1] + b1v, 0.f); yacc[mt * 2]     = fmaf(x, v1, yacc[mt * 2]);
                    x = fmaxf(acc[mt][nt][2] + b0, 0.f);  yacc[mt * 2 + 1] = fmaf(x, v0, yacc[mt * 2 + 1]);
                    x = fmaxf(acc[mt][nt][3] + b1v, 0.f); yacc[mt * 2 + 1] = fmaf(x, v1, yacc[mt * 2 + 1]);
                    acc[mt][nt][0] = 0.f; acc[mt][nt][1] = 0.f;
                    acc[mt][nt][2] = 0.f; acc[mt][nt][3] = 0.f;
                }
        }
        __syncthreads();
    }

    // reduce across the 4 quad lanes
    #pragma unroll
    for (int i = 0; i < 8; i++) {
        yacc[i] += __shfl_xor_sync(0xffffffffu, yacc[i], 1);
        yacc[i] += __shfl_xor_sync(0xffffffffu, yacc[i], 2);
    }
    if ((lane & 3) == 0) {
        #pragma unroll
        for (int mt = 0; mt < 4; mt++) {
            int r0 = wm * 64 + mt * 16 + (lane >> 2);
            red[r0 * 4 + wn]       = yacc[mt * 2];
            red[(r0 + 8) * 4 + wn] = yacc[mt * 2 + 1];
        }
    }
    __syncthreads();
    if (tid < 128) {
        float s = red[tid * 4] + red[tid * 4 + 1] + red[tid * 4 + 2] + red[tid * 4 + 3];
        g_y[row0 + tid] = s + g_c;
    }
}

// ---------------- Gram partials ----------------
__global__ __launch_bounds__(256) void gram_partial(const float* __restrict__ A) {
    __shared__ float rowS[SSTR];
    __shared__ float yS;
    const int tid = threadIdx.x;
    const int i  = tid >> 1;
    const int jb = (tid & 1) * 64;
    float acc[64];
    #pragma unroll
    for (int jj = 0; jj < 64; jj++) acc[jj] = 0.f;
    float racc = 0.f;

    const int n0 = blockIdx.x * (NROWS / 128);
    for (int n = n0; n < n0 + NROWS / 128; n++) {
        __syncthreads();
        if (tid < SSTR) rowS[tid] = A[(size_t)n * SSTR + tid];
        if (tid == SSTR) yS = g_y[n];
        __syncthreads();
        float ai = rowS[i];
        #pragma unroll
        for (int jj = 0; jj < 64; jj++)
            acc[jj] = fmaf(ai, rowS[jb + jj], acc[jj]);
        if (tid < SSTR) racc = fmaf(rowS[tid], yS, racc);
    }
    float* gp = &g_Gpart[(size_t)blockIdx.x * SSTR * SSTR + i * SSTR + jb];
    #pragma unroll
    for (int jj = 0; jj < 64; jj++) gp[jj] = acc[jj];
    if (tid < SSTR) g_rpart[(size_t)blockIdx.x * SSTR + tid] = racc;
}

__global__ void gram_reduce() {
    int idx = blockIdx.x * blockDim.x + threadIdx.x;
    if (idx < SSTR * SSTR) {
        float s = 0.f;
        #pragma unroll 8
        for (int b = 0; b < 128; b++) s += g_Gpart[(size_t)b * SSTR * SSTR + idx];
        g_G[idx] = s;
    }
    if (idx < SSTR) {
        float s = 0.f;
        #pragma unroll 8
        for (int b = 0; b < 128; b++) s += g_rpart[(size_t)b * SSTR + idx];
        g_r[idx] = s;
    }
}

// ---------------- Cholesky solve ----------------
__global__ __launch_bounds__(128) void solve_kernel(const float* __restrict__ w_struct) {
    __shared__ float T[SSTR * (SSTR + 1) / 2];
    __shared__ float rv[SSTR], wv[SSTR], zv[SSTR];
    const int tid = threadIdx.x;
    const int myb = tid * (tid + 1) / 2;

    for (int j = 0; j <= tid; j++) T[myb + j] = g_G[tid * SSTR + j];
    rv[tid] = g_r[tid];
    __syncthreads();

    for (int k = 0; k < SSTR; k++) {
        const int kb = k * (k + 1) / 2;
        float dk = T[kb + k];
        float s = sqrtf(dk);
        float inv = 1.0f / s;
        __syncthreads();
        if (tid == k) T[kb + k] = s;
        float lik = 0.f;
        if (tid > k) { lik = T[myb + k] * inv; T[myb + k] = lik; }
        __syncthreads();
        if (tid > k) {
            int jb_ = (k + 1) * (k + 2) / 2;
            for (int j = k + 1; j <= tid; j++) {
                T[myb + j] -= lik * T[jb_ + k];
                jb_ += j + 1;
            }
        }
        __syncthreads();
    }

    for (int k = 0; k < SSTR; k++) {
        const int kb = k * (k + 1) / 2;
        if (tid == k) wv[k] = rv[k] / T[kb + k];
        __syncthreads();
        if (tid > k) rv[tid] -= T[myb + k] * wv[k];
        __syncthreads();
    }
    for (int k = SSTR - 1; k >= 0; k--) {
        const int kb = k * (k + 1) / 2;
        if (tid == k) zv[k] = wv[k] / T[kb + k];
        __syncthreads();
        if (tid < k) wv[tid] -= T[kb + tid] * zv[k];
        __syncthreads();
    }
    g_wz[tid] = w_struct[tid] - zv[tid];
}

// ---------------- final: out[n] = y[n] + A[n,:] . wz ----------------
__global__ __launch_bounds__(256) void final_kernel(const float* __restrict__ A,
                                                    float* __restrict__ out) {
    int warp = (blockIdx.x * blockDim.x + threadIdx.x) >> 5;
    int lane = threadIdx.x & 31;
    if (warp >= NROWS) return;
    const float* row = A + (size_t)warp * SSTR;
    float s = 0.f;
    #pragma unroll
    for (int q = 0; q < 4; q++) {
        int sidx = q * 32 + lane;
        s = fmaf(row[sidx], g_wz[sidx], s);
    }
    #pragma unroll
    for (int off = 16; off; off >>= 1) s += __shfl_xor_sync(0xffffffffu, s, off);
    if (lane == 0) out[warp] = g_y[warp] + s;
}

// ---------------- launch ----------------
extern "C" void kernel_launch(void* const* d_in, const int* in_sizes, int n_in,
                              void* d_out, int out_size) {
    const float* structured = (const float*)d_in[0];
    const float* d1         = (const float*)d_in[1];
    const float* W1         = (const float*)d_in[2];
    const float* b1         = (const float*)d_in[3];
    const float* W2         = (const float*)d_in[4];
    const float* b2         = (const float*)d_in[5];
    const float* w_struct   = (const float*)d_in[6];
    const float* w_deep     = (const float*)d_in[7];
    float* out = (float*)d_out;

    cudaFuncSetAttribute(mlp_tc, cudaFuncAttributeMaxDynamicSharedMemorySize,
                         SMEM_TOTAL);

    head_kernel<<<(HID + 255) / 256, 256>>>(W2, b2, w_deep);
    conv_d1h<<<(int)((size_t)NROWS * DINV / 4 / 256), 256>>>(d1);
    conv_W1h<<<(int)((size_t)DINV * HID / 4 / 256), 256>>>(W1);
    mlp_tc<<<NROWS / 128, 256, SMEM_TOTAL>>>(b1);
    gram_partial<<<128, 256>>>(structured);
    gram_reduce<<<(SSTR * SSTR + 255) / 256, 256>>>();
    solve_kernel<<<1, 128>>>(w_struct);
    final_kernel<<<(NROWS * 32) / 256, 256>>>(structured, out);
}

// round 8
// speedup vs baseline: 6.3261x; 2.5133x over previous
#include <cuda_runtime.h>
#include <cuda_fp16.h>
#include <math.h>
#include <stdint.h>

// Problem dims
#define NROWS 65536
#define SSTR  128
#define DINV  512
#define HID   1024
#define DOUTV 256

// ---------------- scratch (device globals; no allocation) ----------------
__device__ float g_v[HID];            // W2 @ w_deep
__device__ float g_c;                 // b2 . w_deep
__device__ float g_y[NROWS];          // Uhat @ w_deep
__device__ float g_Gpart[64 * SSTR * SSTR];
__device__ float g_rpart[64 * SSTR];
__device__ float g_G[SSTR * SSTR];
__device__ float g_r[SSTR];
__device__ float g_wz[SSTR];

// fp16 copy of W1 (d1 conversion now fused into mlp_tc)
__device__ __half g_W1h[(size_t)DINV * HID];     // [K][H]

// ---------------- PTX helpers ----------------
__device__ __forceinline__ uint32_t smem_u32(const void* p) {
    uint32_t a;
    asm("{ .reg .u64 t; cvta.to.shared.u64 t, %1; cvt.u32.u64 %0, t; }"
        : "=r"(a) : "l"(p));
    return a;
}
__device__ __forceinline__ void cp16(uint32_t dst, const void* src) {
    asm volatile("cp.async.cg.shared.global [%0], [%1], 16;" :: "r"(dst), "l"(src));
}
__device__ __forceinline__ void ldsm4(uint32_t r[4], uint32_t addr) {
    asm volatile("ldmatrix.sync.aligned.m8n8.x4.shared.b16 {%0,%1,%2,%3}, [%4];"
        : "=r"(r[0]), "=r"(r[1]), "=r"(r[2]), "=r"(r[3]) : "r"(addr));
}
__device__ __forceinline__ void ldsm4t(uint32_t r[4], uint32_t addr) {
    asm volatile("ldmatrix.sync.aligned.m8n8.x4.trans.shared.b16 {%0,%1,%2,%3}, [%4];"
        : "=r"(r[0]), "=r"(r[1]), "=r"(r[2]), "=r"(r[3]) : "r"(addr));
}
__device__ __forceinline__ void mma16816(float c[4], const uint32_t a[4],
                                         uint32_t b0, uint32_t b1) {
    asm volatile(
        "mma.sync.aligned.m16n8k16.row.col.f32.f16.f16.f32 "
        "{%0,%1,%2,%3}, {%4,%5,%6,%7}, {%8,%9}, {%0,%1,%2,%3};"
        : "+f"(c[0]), "+f"(c[1]), "+f"(c[2]), "+f"(c[3])
        : "r"(a[0]), "r"(a[1]), "r"(a[2]), "r"(a[3]), "r"(b0), "r"(b1));
}
__device__ __forceinline__ void mma_tf32(float c[4], uint32_t a0, uint32_t a1,
                                         uint32_t a2, uint32_t a3,
                                         uint32_t b0, uint32_t b1) {
    asm volatile(
        "mma.sync.aligned.m16n8k8.row.col.f32.tf32.tf32.f32 "
        "{%0,%1,%2,%3}, {%4,%5,%6,%7}, {%8,%9}, {%0,%1,%2,%3};"
        : "+f"(c[0]), "+f"(c[1]), "+f"(c[2]), "+f"(c[3])
        : "r"(a0), "r"(a1), "r"(a2), "r"(a3), "r"(b0), "r"(b1));
}
__device__ __forceinline__ uint32_t cvt_tf32(float f) {
    uint32_t u;
    asm("cvt.rna.tf32.f32 %0, %1;" : "=r"(u) : "f"(f));
    return u;
}
__device__ __forceinline__ uint32_t h2raw(__half2 h) {
    return *reinterpret_cast<uint32_t*>(&h);
}

// mlp smem layout (dynamic)
#define SB_A     0u                     // A resident: 128 x 512 fp16 = 131072
#define SB_B     131072u                // B double-buffered: 2 x 32768
#define SB_BV    196608u
#define SB_V     200704u
#define SB_RED   204800u
#define SMEM_TOTAL 206848u

// ---------------- kernel A: v = W2 @ w_deep, c = b2 . w_deep ----------------
__global__ void head_kernel(const float* __restrict__ W2,
                            const float* __restrict__ b2,
                            const float* __restrict__ w_deep) {
    int h = blockIdx.x * blockDim.x + threadIdx.x;
    if (h < HID) {
        const float* wrow = W2 + (size_t)h * DOUTV;
        float s = 0.f;
        #pragma unroll 4
        for (int d = 0; d < DOUTV; d++) s = fmaf(wrow[d], __ldg(&w_deep[d]), s);
        g_v[h] = s;
    }
    if (h == 0) {
        float c = 0.f;
        for (int d = 0; d < DOUTV; d++) c = fmaf(b2[d], w_deep[d], c);
        g_c = c;
    }
}

// ---------------- conversion: W1 -> fp16 ----------------
__global__ __launch_bounds__(256) void conv_W1h(const float* __restrict__ W1) {
    size_t i = (size_t)blockIdx.x * 256 + threadIdx.x;
    float4 f = reinterpret_cast<const float4*>(W1)[i];
    __half2 a = __floats2half2_rn(f.x, f.y);
    __half2 b = __floats2half2_rn(f.z, f.w);
    reinterpret_cast<__half2*>(g_W1h)[2 * i]     = a;
    reinterpret_cast<__half2*>(g_W1h)[2 * i + 1] = b;
}

// ---------------- tensor-core MLP reduce (mma.sync fp16) ----------------
__device__ __forceinline__ void loadB_chunk(int s, uint32_t sbB, int tid) {
    int ht = s >> 3, kc = s & 7;
    uint32_t base = sbB + (uint32_t)(s & 1) * 32768u;
    #pragma unroll
    for (int i = 0; i < 8; i++) {
        int c = tid + i * 256;
        int kr = c >> 5, p = c & 31;
        uint32_t dst = base + kr * 512 + ((uint32_t)(p ^ (kr & 7)) << 4);
        cp16(dst, g_W1h + (size_t)(kc * 64 + kr) * HID + ht * 256 + p * 8);
    }
}

__global__ void __launch_bounds__(256, 1) mlp_tc(const float* __restrict__ d1,
                                                 const float* __restrict__ b1) {
    extern __shared__ char smem[];
    const uint32_t sb = smem_u32(smem);
    const uint32_t sbA = sb + SB_A;
    const uint32_t sbB = sb + SB_B;
    float* bvS = (float*)(smem + SB_BV);
    float* vS  = (float*)(smem + SB_V);
    float* red = (float*)(smem + SB_RED);

    const int tid = threadIdx.x;
    const int lane = tid & 31;
    const int wid = tid >> 5;
    const int wm = wid & 1;
    const int wn = wid >> 1;
    const int row0 = blockIdx.x * 128;

    // prologue: load d1 fp32, convert to fp16, store swizzled (fused conversion)
    #pragma unroll 8
    for (int i = 0; i < 64; i++) {
        int u = tid + i * 256;        // 16B fp32 unit: 4 floats
        int r = u >> 7, seg = u & 127;
        float4 f = reinterpret_cast<const float4*>(
            d1 + (size_t)(row0 + r) * DINV)[seg];
        uint32_t q0 = h2raw(__floats2half2_rn(f.x, f.y));
        uint32_t q1 = h2raw(__floats2half2_rn(f.z, f.w));
        uint32_t dst = sbA + r * 1024 +
                       (((uint32_t)((seg >> 1) ^ (r & 7))) << 4) + (seg & 1) * 8;
        asm volatile("st.shared.v2.b32 [%0], {%1,%2};"
                     :: "r"(dst), "r"(q0), "r"(q1));
    }
    loadB_chunk(0, sbB, tid);
    asm volatile("cp.async.commit_group;" ::: "memory");
    for (int i = tid; i < HID; i += 256) {
        bvS[i] = __ldg(&b1[i]);
        vS[i]  = g_v[i];
    }

    float acc[4][8][4];
    #pragma unroll
    for (int mt = 0; mt < 4; mt++)
        #pragma unroll
        for (int nt = 0; nt < 8; nt++)
            #pragma unroll
            for (int q = 0; q < 4; q++) acc[mt][nt][q] = 0.f;
    float yacc[8];
    #pragma unroll
    for (int i = 0; i < 8; i++) yacc[i] = 0.f;

    for (int s = 0; s < 32; s++) {
        if (s + 1 < 32) {
            loadB_chunk(s + 1, sbB, tid);
            asm volatile("cp.async.commit_group;" ::: "memory");
            asm volatile("cp.async.wait_group 1;" ::: "memory");
        } else {
            asm volatile("cp.async.wait_group 0;" ::: "memory");
        }
        __syncthreads();

        const uint32_t bb = sbB + (uint32_t)(s & 1) * 32768u;
        #pragma unroll
        for (int k16 = 0; k16 < 4; k16++) {
            uint32_t af[4][4], bf[4][4];
            #pragma unroll
            for (int mt = 0; mt < 4; mt++) {
                int r = wm * 64 + mt * 16 + (lane & 15);
                int kch = (s & 7) * 8 + k16 * 2 + (lane >> 4);
                ldsm4(af[mt], sbA + r * 1024 + ((uint32_t)(kch ^ (r & 7)) << 4));
            }
            #pragma unroll
            for (int np = 0; np < 4; np++) {
                int m = lane >> 3;
                int kr = k16 * 16 + ((m & 1) << 3) + (lane & 7);
                int nch = wn * 8 + np * 2 + (m >> 1);
                ldsm4t(bf[np], bb + kr * 512 + ((uint32_t)(nch ^ (kr & 7)) << 4));
            }
            #pragma unroll
            for (int mt = 0; mt < 4; mt++)
                #pragma unroll
                for (int nt = 0; nt < 8; nt++) {
                    int np = nt >> 1, od = nt & 1;
                    mma16816(acc[mt][nt], af[mt], bf[np][od * 2], bf[np][od * 2 + 1]);
                }
        }

        if ((s & 7) == 7) {
            int ht = s >> 3;
            #pragma unroll
            for (int mt = 0; mt < 4; mt++)
                #pragma unroll
                for (int nt = 0; nt < 8; nt++) {
                    int np = nt >> 1, od = nt & 1;
                    int col = ht * 256 + wn * 64 + np * 16 + od * 8 + (lane & 3) * 2;
                    float b0 = bvS[col], b1v = bvS[col + 1];
                    float v0 = vS[col], v1 = vS[col + 1];
                    float x;
                    x = fmaxf(acc[mt][nt][0] + b0, 0.f);  yacc[mt * 2]     = fmaf(x, v0, yacc[mt * 2]);
                    x = fmaxf(acc[mt][nt][1] + b1v, 0.f); yacc[mt * 2]     = fmaf(x, v1, yacc[mt * 2]);
                    x = fmaxf(acc[mt][nt][2] + b0, 0.f);  yacc[mt * 2 + 1] = fmaf(x, v0, yacc[mt * 2 + 1]);
                    x = fmaxf(acc[mt][nt][3] + b1v, 0.f); yacc[mt * 2 + 1] = fmaf(x, v1, yacc[mt * 2 + 1]);
                    acc[mt][nt][0] = 0.f; acc[mt][nt][1] = 0.f;
                    acc[mt][nt][2] = 0.f; acc[mt][nt][3] = 0.f;
                }
        }
        __syncthreads();
    }

    #pragma unroll
    for (int i = 0; i < 8; i++) {
        yacc[i] += __shfl_xor_sync(0xffffffffu, yacc[i], 1);
        yacc[i] += __shfl_xor_sync(0xffffffffu, yacc[i], 2);
    }
    if ((lane & 3) == 0) {
        #pragma unroll
        for (int mt = 0; mt < 4; mt++) {
            int r0 = wm * 64 + mt * 16 + (lane >> 2);
            red[r0 * 4 + wn]       = yacc[mt * 2];
            red[(r0 + 8) * 4 + wn] = yacc[mt * 2 + 1];
        }
    }
    __syncthreads();
    if (tid < 128) {
        float s = red[tid * 4] + red[tid * 4 + 1] + red[tid * 4 + 2] + red[tid * 4 + 3];
        g_y[row0 + tid] = s + g_c;
    }
}

// ---------------- Gram via tf32 mma: G partials + r partials ----------------
// 64 blocks x 1024 rows. Stages of 64 rows, cp.async double-buffered.
// Smem row stride = 136 floats (544B): conflict-free tf32 frag loads.
#define GPAD 136
#define GBUF_BYTES (64 * GPAD * 4)   // 34816
#define GRAM_SMEM (2 * GBUF_BYTES)   // 69632

__device__ __forceinline__ void gram_load_stage(int s, uint32_t sb, int n0, int tid,
                                                const float* A) {
    uint32_t base = sb + (uint32_t)(s & 1) * GBUF_BYTES;
    int ns = n0 + s * 64;
    #pragma unroll
    for (int i = 0; i < 8; i++) {
        int c = tid + i * 256;
        int row = c >> 5, seg = c & 31;
        cp16(base + row * (GPAD * 4) + seg * 16,
             A + (size_t)(ns + row) * SSTR + seg * 4);
    }
}

__global__ void __launch_bounds__(256, 1) gram_mma(const float* __restrict__ A) {
    extern __shared__ char smem[];
    const uint32_t sb = smem_u32(smem);
    const int tid = threadIdx.x;
    const int lane = tid & 31;
    const int w = tid >> 5;
    const int n0 = blockIdx.x * 1024;

    float acc[16][4];
    #pragma unroll
    for (int nt = 0; nt < 16; nt++)
        #pragma unroll
        for (int q = 0; q < 4; q++) acc[nt][q] = 0.f;
    float racc = 0.f;

    gram_load_stage(0, sb, n0, tid, A);
    asm volatile("cp.async.commit_group;" ::: "memory");

    const int colA = lane >> 2;   // 0..7
    const int rowK = lane & 3;    // 0..3
    const int i0 = w * 16;

    for (int s = 0; s < 16; s++) {
        if (s + 1 < 16) {
            gram_load_stage(s + 1, sb, n0, tid, A);
            asm volatile("cp.async.commit_group;" ::: "memory");
            asm volatile("cp.async.wait_group 1;" ::: "memory");
        } else {
            asm volatile("cp.async.wait_group 0;" ::: "memory");
        }
        __syncthreads();
        const float* S = (const float*)(smem + (size_t)(s & 1) * GBUF_BYTES);

        #pragma unroll
        for (int ks = 0; ks < 8; ks++) {
            int kb = ks * 8;
            const float* Slo = S + (kb + rowK) * GPAD;
            const float* Shi = S + (kb + 4 + rowK) * GPAD;
            uint32_t a0 = cvt_tf32(Slo[i0 + colA]);
            uint32_t a1 = cvt_tf32(Slo[i0 + 8 + colA]);
            uint32_t a2 = cvt_tf32(Shi[i0 + colA]);
            uint32_t a3 = cvt_tf32(Shi[i0 + 8 + colA]);
            #pragma unroll
            for (int nt = 0; nt < 16; nt++) {
                uint32_t b0 = cvt_tf32(Slo[nt * 8 + colA]);
                uint32_t b1 = cvt_tf32(Shi[nt * 8 + colA]);
                mma_tf32(acc[nt], a0, a1, a2, a3, b0, b1);
            }
        }
        // r partial (warps 0-3): r[j] += A[n][j] * y[n]
        if (tid < 128) {
            const int nbase = n0 + s * 64;
            #pragma unroll 8
            for (int n = 0; n < 64; n++)
                racc = fmaf(S[n * GPAD + tid], __ldg(&g_y[nbase + n]), racc);
        }
        __syncthreads();
    }

    float* gp = g_Gpart + (size_t)blockIdx.x * (SSTR * SSTR);
    int r_lo = i0 + (lane >> 2);
    int cb = (lane & 3) * 2;
    #pragma unroll
    for (int nt = 0; nt < 16; nt++) {
        int j = nt * 8 + cb;
        float2 lo = make_float2(acc[nt][0], acc[nt][1]);
        float2 hi = make_float2(acc[nt][2], acc[nt][3]);
        *reinterpret_cast<float2*>(&gp[r_lo * SSTR + j]) = lo;
        *reinterpret_cast<float2*>(&gp[(r_lo + 8) * SSTR + j]) = hi;
    }
    if (tid < 128) g_rpart[blockIdx.x * SSTR + tid] = racc;
}

__global__ void __launch_bounds__(256) gram_reduce() {
    int idx = blockIdx.x * 256 + threadIdx.x;   // 0..16383
    float s = 0.f;
    #pragma unroll 16
    for (int b = 0; b < 64; b++) s += g_Gpart[(size_t)b * (SSTR * SSTR) + idx];
    g_G[idx] = s;
    if (idx < SSTR) {
        float t = 0.f;
        #pragma unroll 16
        for (int b = 0; b < 64; b++) t += g_rpart[b * SSTR + idx];
        g_r[idx] = t;
    }
}

// ---------------- CG solve: G z = r (kappa ~ 1.2) ----------------
#define SOLVE_SMEM (128 * 129 * 4 + 128 * 4 + 64)

__device__ __forceinline__ float bsum128(float x, float* redS, int tid) {
    #pragma unroll
    for (int o = 16; o; o >>= 1) x += __shfl_xor_sync(0xffffffffu, x, o);
    __syncthreads();
    if ((tid & 31) == 0) redS[tid >> 5] = x;
    __syncthreads();
    return redS[0] + redS[1] + redS[2] + redS[3];
}

__global__ void __launch_bounds__(128) solve_cg(const float* __restrict__ w_struct) {
    extern __shared__ float sm[];
    float* Gs   = sm;                 // 128 rows, stride 129 (bank-conflict-free)
    float* pS   = sm + 128 * 129;
    float* redS = pS + 128;
    const int tid = threadIdx.x;

    for (int i = tid; i < SSTR * SSTR; i += 128)
        Gs[(i >> 7) * 129 + (i & 127)] = g_G[i];
    float res = g_r[tid];
    float z = 0.f, p = res;
    __syncthreads();
    float rs = bsum128(res * res, redS, tid);

    for (int it = 0; it < 20; it++) {
        pS[tid] = p;
        __syncthreads();
        float q = 0.f;
        const float* row = Gs + tid * 129;
        #pragma unroll 8
        for (int j = 0; j < SSTR; j++) q = fmaf(row[j], pS[j], q);
        float pq = bsum128(p * q, redS, tid);
        float alpha = rs / pq;
        z   = fmaf(alpha, p, z);
        res = fmaf(-alpha, q, res);
        float rs_new = bsum128(res * res, redS, tid);
        float beta = rs_new / rs;
        rs = rs_new;
        p = fmaf(beta, p, res);
        __syncthreads();
    }
    g_wz[tid] = w_struct[tid] - z;
}

// ---------------- final: out[n] = y[n] + A[n,:] . wz ----------------
__global__ __launch_bounds__(256) void final_kernel(const float* __restrict__ A,
                                                    float* __restrict__ out) {
    int warp = (blockIdx.x * blockDim.x + threadIdx.x) >> 5;
    int lane = threadIdx.x & 31;
    if (warp >= NROWS) return;
    const float* row = A + (size_t)warp * SSTR;
    float s = 0.f;
    #pragma unroll
    for (int q = 0; q < 4; q++) {
        int sidx = q * 32 + lane;
        s = fmaf(row[sidx], g_wz[sidx], s);
    }
    #pragma unroll
    for (int off = 16; off; off >>= 1) s += __shfl_xor_sync(0xffffffffu, s, off);
    if (lane == 0) out[warp] = g_y[warp] + s;
}

// ---------------- launch ----------------
extern "C" void kernel_launch(void* const* d_in, const int* in_sizes, int n_in,
                              void* d_out, int out_size) {
    const float* structured = (const float*)d_in[0];
    const float* d1         = (const float*)d_in[1];
    const float* W1         = (const float*)d_in[2];
    const float* b1         = (const float*)d_in[3];
    const float* W2         = (const float*)d_in[4];
    const float* b2         = (const float*)d_in[5];
    const float* w_struct   = (const float*)d_in[6];
    const float* w_deep     = (const float*)d_in[7];
    float* out = (float*)d_out;

    cudaFuncSetAttribute(mlp_tc, cudaFuncAttributeMaxDynamicSharedMemorySize,
                         SMEM_TOTAL);
    cudaFuncSetAttribute(gram_mma, cudaFuncAttributeMaxDynamicSharedMemorySize,
                         GRAM_SMEM);
    cudaFuncSetAttribute(solve_cg, cudaFuncAttributeMaxDynamicSharedMemorySize,
                         SOLVE_SMEM);

    head_kernel<<<(HID + 255) / 256, 256>>>(W2, b2, w_deep);
    conv_W1h<<<(int)((size_t)DINV * HID / 4 / 256), 256>>>(W1);
    mlp_tc<<<NROWS / 128, 256, SMEM_TOTAL>>>(d1, b1);
    gram_mma<<<NROWS / 1024, 256, GRAM_SMEM>>>(structured);
    gram_reduce<<<SSTR * SSTR / 256, 256>>>();
    solve_cg<<<1, 128, SOLVE_SMEM>>>(w_struct);
    final_kernel<<<(NROWS * 32) / 256, 256>>>(structured, out);
}

// round 9
// speedup vs baseline: 7.0847x; 1.1199x over previous
#include <cuda_runtime.h>
#include <cuda_fp16.h>
#include <math.h>
#include <stdint.h>

// Problem dims
#define NROWS 65536
#define SSTR  128
#define DINV  512
#define HID   1024
#define DOUTV 256

#define GBLOCKS 256

// ---------------- scratch (device globals; no allocation) ----------------
__device__ float g_v[HID];            // W2 @ w_deep
__device__ float g_c;                 // b2 . w_deep
__device__ float g_y[NROWS];          // Uhat @ w_deep
__device__ float g_Gpart[(size_t)GBLOCKS * SSTR * SSTR];   // 16.8 MB
__device__ float g_rpart[GBLOCKS * SSTR];
__device__ float g_G[SSTR * SSTR];
__device__ float g_wz[SSTR];

// fp16 copy of W1 (d1 conversion fused into mlp_tc)
__device__ __half g_W1h[(size_t)DINV * HID];     // [K][H]

// ---------------- PTX helpers ----------------
__device__ __forceinline__ uint32_t smem_u32(const void* p) {
    uint32_t a;
    asm("{ .reg .u64 t; cvta.to.shared.u64 t, %1; cvt.u32.u64 %0, t; }"
        : "=r"(a) : "l"(p));
    return a;
}
__device__ __forceinline__ void cp16(uint32_t dst, const void* src) {
    asm volatile("cp.async.cg.shared.global [%0], [%1], 16;" :: "r"(dst), "l"(src));
}
__device__ __forceinline__ void ldsm4(uint32_t r[4], uint32_t addr) {
    asm volatile("ldmatrix.sync.aligned.m8n8.x4.shared.b16 {%0,%1,%2,%3}, [%4];"
        : "=r"(r[0]), "=r"(r[1]), "=r"(r[2]), "=r"(r[3]) : "r"(addr));
}
__device__ __forceinline__ void ldsm4t(uint32_t r[4], uint32_t addr) {
    asm volatile("ldmatrix.sync.aligned.m8n8.x4.trans.shared.b16 {%0,%1,%2,%3}, [%4];"
        : "=r"(r[0]), "=r"(r[1]), "=r"(r[2]), "=r"(r[3]) : "r"(addr));
}
__device__ __forceinline__ void mma16816(float c[4], const uint32_t a[4],
                                         uint32_t b0, uint32_t b1) {
    asm volatile(
        "mma.sync.aligned.m16n8k16.row.col.f32.f16.f16.f32 "
        "{%0,%1,%2,%3}, {%4,%5,%6,%7}, {%8,%9}, {%0,%1,%2,%3};"
        : "+f"(c[0]), "+f"(c[1]), "+f"(c[2]), "+f"(c[3])
        : "r"(a[0]), "r"(a[1]), "r"(a[2]), "r"(a[3]), "r"(b0), "r"(b1));
}
__device__ __forceinline__ void mma_tf32(float c[4], uint32_t a0, uint32_t a1,
                                         uint32_t a2, uint32_t a3,
                                         uint32_t b0, uint32_t b1) {
    asm volatile(
        "mma.sync.aligned.m16n8k8.row.col.f32.tf32.tf32.f32 "
        "{%0,%1,%2,%3}, {%4,%5,%6,%7}, {%8,%9}, {%0,%1,%2,%3};"
        : "+f"(c[0]), "+f"(c[1]), "+f"(c[2]), "+f"(c[3])
        : "r"(a0), "r"(a1), "r"(a2), "r"(a3), "r"(b0), "r"(b1));
}
__device__ __forceinline__ uint32_t cvt_tf32(float f) {
    uint32_t u;
    asm("cvt.rna.tf32.f32 %0, %1;" : "=r"(u) : "f"(f));
    return u;
}
__device__ __forceinline__ uint32_t h2raw(__half2 h) {
    return *reinterpret_cast<uint32_t*>(&h);
}

// mlp smem layout (dynamic)
#define SB_A     0u                     // A resident: 128 x 512 fp16 = 131072
#define SB_B     131072u                // B double-buffered: 2 x 32768
#define SB_BV    196608u
#define SB_V     200704u
#define SB_RED   204800u
#define SMEM_TOTAL 206848u

// ---------------- kernel A: v = W2 @ w_deep, c = b2 . w_deep ----------------
__global__ void head_kernel(const float* __restrict__ W2,
                            const float* __restrict__ b2,
                            const float* __restrict__ w_deep) {
    int h = blockIdx.x * blockDim.x + threadIdx.x;
    if (h < HID) {
        const float* wrow = W2 + (size_t)h * DOUTV;
        float s = 0.f;
        #pragma unroll 4
        for (int d = 0; d < DOUTV; d++) s = fmaf(wrow[d], __ldg(&w_deep[d]), s);
        g_v[h] = s;
    }
    if (h == 0) {
        float c = 0.f;
        for (int d = 0; d < DOUTV; d++) c = fmaf(b2[d], w_deep[d], c);
        g_c = c;
    }
}

// ---------------- conversion: W1 -> fp16 ----------------
__global__ __launch_bounds__(256) void conv_W1h(const float* __restrict__ W1) {
    size_t i = (size_t)blockIdx.x * 256 + threadIdx.x;
    float4 f = reinterpret_cast<const float4*>(W1)[i];
    __half2 a = __floats2half2_rn(f.x, f.y);
    __half2 b = __floats2half2_rn(f.z, f.w);
    reinterpret_cast<__half2*>(g_W1h)[2 * i]     = a;
    reinterpret_cast<__half2*>(g_W1h)[2 * i + 1] = b;
}

// ---------------- tensor-core MLP reduce (mma.sync fp16, 16 warps) ----------------
// CTA: 512 threads = 16 warps (wm 0..3 x wn 0..3); warp tile 32x64.
// CTA tile: M=128 rows (A resident, K=512), N=256 per h-tile, 4 h-tiles.
__device__ __forceinline__ void loadB_chunk(int s, uint32_t sbB, int tid) {
    int ht = s >> 3, kc = s & 7;
    uint32_t base = sbB + (uint32_t)(s & 1) * 32768u;
    #pragma unroll
    for (int i = 0; i < 4; i++) {
        int c = tid + i * 512;
        int kr = c >> 5, p = c & 31;
        uint32_t dst = base + kr * 512 + ((uint32_t)(p ^ (kr & 7)) << 4);
        cp16(dst, g_W1h + (size_t)(kc * 64 + kr) * HID + ht * 256 + p * 8);
    }
}

__global__ void __launch_bounds__(512, 1) mlp_tc(const float* __restrict__ d1,
                                                 const float* __restrict__ b1) {
    extern __shared__ char smem[];
    const uint32_t sb = smem_u32(smem);
    const uint32_t sbA = sb + SB_A;
    const uint32_t sbB = sb + SB_B;
    float* bvS = (float*)(smem + SB_BV);
    float* vS  = (float*)(smem + SB_V);
    float* red = (float*)(smem + SB_RED);

    const int tid = threadIdx.x;
    const int lane = tid & 31;
    const int wid = tid >> 5;
    const int wm = wid & 3;       // M quarter (32 rows)
    const int wn = wid >> 2;      // N quarter (64 cols)
    const int row0 = blockIdx.x * 128;

    // prologue: load d1 fp32, convert to fp16, store swizzled (fused conversion)
    #pragma unroll 8
    for (int i = 0; i < 32; i++) {
        int u = tid + i * 512;        // 16B fp32 unit: 4 floats
        int r = u >> 7, seg = u & 127;
        float4 f = reinterpret_cast<const float4*>(
            d1 + (size_t)(row0 + r) * DINV)[seg];
        uint32_t q0 = h2raw(__floats2half2_rn(f.x, f.y));
        uint32_t q1 = h2raw(__floats2half2_rn(f.z, f.w));
        uint32_t dst = sbA + r * 1024 +
                       (((uint32_t)((seg >> 1) ^ (r & 7))) << 4) + (seg & 1) * 8;
        asm volatile("st.shared.v2.b32 [%0], {%1,%2};"
                     :: "r"(dst), "r"(q0), "r"(q1));
    }
    loadB_chunk(0, sbB, tid);
    asm volatile("cp.async.commit_group;" ::: "memory");
    for (int i = tid; i < HID; i += 512) {
        bvS[i] = __ldg(&b1[i]);
        vS[i]  = g_v[i];
    }

    float acc[2][8][4];
    #pragma unroll
    for (int mt = 0; mt < 2; mt++)
        #pragma unroll
        for (int nt = 0; nt < 8; nt++)
            #pragma unroll
            for (int q = 0; q < 4; q++) acc[mt][nt][q] = 0.f;
    float yacc[4];
    #pragma unroll
    for (int i = 0; i < 4; i++) yacc[i] = 0.f;

    for (int s = 0; s < 32; s++) {
        if (s + 1 < 32) {
            loadB_chunk(s + 1, sbB, tid);
            asm volatile("cp.async.commit_group;" ::: "memory");
            asm volatile("cp.async.wait_group 1;" ::: "memory");
        } else {
            asm volatile("cp.async.wait_group 0;" ::: "memory");
        }
        __syncthreads();

        const uint32_t bb = sbB + (uint32_t)(s & 1) * 32768u;
        #pragma unroll
        for (int k16 = 0; k16 < 4; k16++) {
            uint32_t af[2][4], bf[4][4];
            #pragma unroll
            for (int mt = 0; mt < 2; mt++) {
                int r = wm * 32 + mt * 16 + (lane & 15);
                int kch = (s & 7) * 8 + k16 * 2 + (lane >> 4);
                ldsm4(af[mt], sbA + r * 1024 + ((uint32_t)(kch ^ (r & 7)) << 4));
            }
            #pragma unroll
            for (int np = 0; np < 4; np++) {
                int m = lane >> 3;
                int kr = k16 * 16 + ((m & 1) << 3) + (lane & 7);
                int nch = wn * 8 + np * 2 + (m >> 1);
                ldsm4t(bf[np], bb + kr * 512 + ((uint32_t)(nch ^ (kr & 7)) << 4));
            }
            #pragma unroll
            for (int mt = 0; mt < 2; mt++)
                #pragma unroll
                for (int nt = 0; nt < 8; nt++) {
                    int np = nt >> 1, od = nt & 1;
                    mma16816(acc[mt][nt], af[mt], bf[np][od * 2], bf[np][od * 2 + 1]);
                }
        }

        if ((s & 7) == 7) {
            int ht = s >> 3;
            #pragma unroll
            for (int mt = 0; mt < 2; mt++)
                #pragma unroll
                for (int nt = 0; nt < 8; nt++) {
                    int np = nt >> 1, od = nt & 1;
                    int col = ht * 256 + wn * 64 + np * 16 + od * 8 + (lane & 3) * 2;
                    float b0 = bvS[col], b1v = bvS[col + 1];
                    float v0 = vS[col], v1 = vS[col + 1];
                    float x;
                    x = fmaxf(acc[mt][nt][0] + b0, 0.f);  yacc[mt * 2]     = fmaf(x, v0, yacc[mt * 2]);
                    x = fmaxf(acc[mt][nt][1] + b1v, 0.f); yacc[mt * 2]     = fmaf(x, v1, yacc[mt * 2]);
                    x = fmaxf(acc[mt][nt][2] + b0, 0.f);  yacc[mt * 2 + 1] = fmaf(x, v0, yacc[mt * 2 + 1]);
                    x = fmaxf(acc[mt][nt][3] + b1v, 0.f); yacc[mt * 2 + 1] = fmaf(x, v1, yacc[mt * 2 + 1]);
                    acc[mt][nt][0] = 0.f; acc[mt][nt][1] = 0.f;
                    acc[mt][nt][2] = 0.f; acc[mt][nt][3] = 0.f;
                }
        }
        __syncthreads();
    }

    // reduce across the 4 quad lanes
    #pragma unroll
    for (int i = 0; i < 4; i++) {
        yacc[i] += __shfl_xor_sync(0xffffffffu, yacc[i], 1);
        yacc[i] += __shfl_xor_sync(0xffffffffu, yacc[i], 2);
    }
    if ((lane & 3) == 0) {
        #pragma unroll
        for (int mt = 0; mt < 2; mt++) {
            int r0 = wm * 32 + mt * 16 + (lane >> 2);
            red[r0 * 4 + wn]       = yacc[mt * 2];
            red[(r0 + 8) * 4 + wn] = yacc[mt * 2 + 1];
        }
    }
    __syncthreads();
    if (tid < 128) {
        float s = red[tid * 4] + red[tid * 4 + 1] + red[tid * 4 + 2] + red[tid * 4 + 3];
        g_y[row0 + tid] = s + g_c;
    }
}

// ---------------- Gram via tf32 mma: G partials + r partials ----------------
// GBLOCKS blocks x 256 rows each. Stages of 64 rows, cp.async double-buffered.
#define GPAD 136
#define GBUF_BYTES (64 * GPAD * 4)   // 34816
#define GRAM_SMEM (2 * GBUF_BYTES)   // 69632
#define GSTAGES 4                    // 256 rows / 64

__device__ __forceinline__ void gram_load_stage(int s, uint32_t sb, int n0, int tid,
                                                const float* A) {
    uint32_t base = sb + (uint32_t)(s & 1) * GBUF_BYTES;
    int ns = n0 + s * 64;
    #pragma unroll
    for (int i = 0; i < 8; i++) {
        int c = tid + i * 256;
        int row = c >> 5, seg = c & 31;
        cp16(base + row * (GPAD * 4) + seg * 16,
             A + (size_t)(ns + row) * SSTR + seg * 4);
    }
}

__global__ void __launch_bounds__(256, 1) gram_mma(const float* __restrict__ A) {
    extern __shared__ char smem[];
    const uint32_t sb = smem_u32(smem);
    const int tid = threadIdx.x;
    const int lane = tid & 31;
    const int w = tid >> 5;
    const int n0 = blockIdx.x * (NROWS / GBLOCKS);

    float acc[16][4];
    #pragma unroll
    for (int nt = 0; nt < 16; nt++)
        #pragma unroll
        for (int q = 0; q < 4; q++) acc[nt][q] = 0.f;
    float racc = 0.f;

    gram_load_stage(0, sb, n0, tid, A);
    asm volatile("cp.async.commit_group;" ::: "memory");

    const int colA = lane >> 2;   // 0..7
    const int rowK = lane & 3;    // 0..3
    const int i0 = w * 16;

    for (int s = 0; s < GSTAGES; s++) {
        if (s + 1 < GSTAGES) {
            gram_load_stage(s + 1, sb, n0, tid, A);
            asm volatile("cp.async.commit_group;" ::: "memory");
            asm volatile("cp.async.wait_group 1;" ::: "memory");
        } else {
            asm volatile("cp.async.wait_group 0;" ::: "memory");
        }
        __syncthreads();
        const float* S = (const float*)(smem + (size_t)(s & 1) * GBUF_BYTES);

        #pragma unroll
        for (int ks = 0; ks < 8; ks++) {
            int kb = ks * 8;
            const float* Slo = S + (kb + rowK) * GPAD;
            const float* Shi = S + (kb + 4 + rowK) * GPAD;
            uint32_t a0 = cvt_tf32(Slo[i0 + colA]);
            uint32_t a1 = cvt_tf32(Slo[i0 + 8 + colA]);
            uint32_t a2 = cvt_tf32(Shi[i0 + colA]);
            uint32_t a3 = cvt_tf32(Shi[i0 + 8 + colA]);
            #pragma unroll
            for (int nt = 0; nt < 16; nt++) {
                uint32_t b0 = cvt_tf32(Slo[nt * 8 + colA]);
                uint32_t b1 = cvt_tf32(Shi[nt * 8 + colA]);
                mma_tf32(acc[nt], a0, a1, a2, a3, b0, b1);
            }
        }
        // r partial (warps 0-3): r[j] += A[n][j] * y[n]
        if (tid < 128) {
            const int nbase = n0 + s * 64;
            #pragma unroll 8
            for (int n = 0; n < 64; n++)
                racc = fmaf(S[n * GPAD + tid], __ldg(&g_y[nbase + n]), racc);
        }
        __syncthreads();
    }

    float* gp = g_Gpart + (size_t)blockIdx.x * (SSTR * SSTR);
    int r_lo = i0 + (lane >> 2);
    int cb = (lane & 3) * 2;
    #pragma unroll
    for (int nt = 0; nt < 16; nt++) {
        int j = nt * 8 + cb;
        float2 lo = make_float2(acc[nt][0], acc[nt][1]);
        float2 hi = make_float2(acc[nt][2], acc[nt][3]);
        *reinterpret_cast<float2*>(&gp[r_lo * SSTR + j]) = lo;
        *reinterpret_cast<float2*>(&gp[(r_lo + 8) * SSTR + j]) = hi;
    }
    if (tid < 128) g_rpart[blockIdx.x * SSTR + tid] = racc;
}

// 2D reduce: 256 blocks x (64 idx, 4-way partial split)
__global__ void __launch_bounds__(256) gram_reduce() {
    __shared__ float red[4][64];
    const int tid = threadIdx.x;
    const int idx = blockIdx.x * 64 + (tid & 63);
    const int q = tid >> 6;
    float s = 0.f;
    #pragma unroll 16
    for (int b = q * 64; b < q * 64 + 64; b++)
        s += g_Gpart[(size_t)b * (SSTR * SSTR) + idx];
    red[q][tid & 63] = s;
    __syncthreads();
    if (tid < 64)
        g_G[blockIdx.x * 64 + tid] =
            red[0][tid] + red[1][tid] + red[2][tid] + red[3][tid];
}

// ---------------- CG solve: G z = r (kappa ~ 1.2) ----------------
#define SOLVE_SMEM (128 * 129 * 4 + 128 * 4 + 64)

__device__ __forceinline__ float bsum128(float x, float* redS, int tid) {
    #pragma unroll
    for (int o = 16; o; o >>= 1) x += __shfl_xor_sync(0xffffffffu, x, o);
    __syncthreads();
    if ((tid & 31) == 0) redS[tid >> 5] = x;
    __syncthreads();
    return redS[0] + redS[1] + redS[2] + redS[3];
}

__global__ void __launch_bounds__(128) solve_cg(const float* __restrict__ w_struct) {
    extern __shared__ float sm[];
    float* Gs   = sm;                 // 128 rows, stride 129
    float* pS   = sm + 128 * 129;
    float* redS = pS + 128;
    const int tid = threadIdx.x;

    for (int i = tid; i < SSTR * SSTR; i += 128)
        Gs[(i >> 7) * 129 + (i & 127)] = g_G[i];
    // reduce r partials here (fused; removes separate pass)
    float res = 0.f;
    #pragma unroll 16
    for (int b = 0; b < GBLOCKS; b++) res += g_rpart[b * SSTR + tid];
    float z = 0.f, p = res;
    __syncthreads();
    float rs = bsum128(res * res, redS, tid);

    for (int it = 0; it < 20; it++) {
        pS[tid] = p;
        __syncthreads();
        float q = 0.f;
        const float* row = Gs + tid * 129;
        #pragma unroll 8
        for (int j = 0; j < SSTR; j++) q = fmaf(row[j], pS[j], q);
        float pq = bsum128(p * q, redS, tid);
        float alpha = rs / pq;
        z   = fmaf(alpha, p, z);
        res = fmaf(-alpha, q, res);
        float rs_new = bsum128(res * res, redS, tid);
        float beta = rs_new / rs;
        rs = rs_new;
        p = fmaf(beta, p, res);
        __syncthreads();
    }
    g_wz[tid] = w_struct[tid] - z;
}

// ---------------- final: out[n] = y[n] + A[n,:] . wz ----------------
__global__ __launch_bounds__(256) void final_kernel(const float* __restrict__ A,
                                                    float* __restrict__ out) {
    int warp = (blockIdx.x * blockDim.x + threadIdx.x) >> 5;
    int lane = threadIdx.x & 31;
    if (warp >= NROWS) return;
    const float4* row = reinterpret_cast<const float4*>(A + (size_t)warp * SSTR);
    float4 a = row[lane];
    float4 wz = reinterpret_cast<const float4*>(g_wz)[lane];
    float s = a.x * wz.x + a.y * wz.y + a.z * wz.z + a.w * wz.w;
    #pragma unroll
    for (int off = 16; off; off >>= 1) s += __shfl_xor_sync(0xffffffffu, s, off);
    if (lane == 0) out[warp] = g_y[warp] + s;
}

// ---------------- launch ----------------
extern "C" void kernel_launch(void* const* d_in, const int* in_sizes, int n_in,
                              void* d_out, int out_size) {
    const float* structured = (const float*)d_in[0];
    const float* d1         = (const float*)d_in[1];
    const float* W1         = (const float*)d_in[2];
    const float* b1         = (const float*)d_in[3];
    const float* W2         = (const float*)d_in[4];
    const float* b2         = (const float*)d_in[5];
    const float* w_struct   = (const float*)d_in[6];
    const float* w_deep     = (const float*)d_in[7];
    float* out = (float*)d_out;

    cudaFuncSetAttribute(mlp_tc, cudaFuncAttributeMaxDynamicSharedMemorySize,
                         SMEM_TOTAL);
    cudaFuncSetAttribute(gram_mma, cudaFuncAttributeMaxDynamicSharedMemorySize,
                         GRAM_SMEM);
    cudaFuncSetAttribute(solve_cg, cudaFuncAttributeMaxDynamicSharedMemorySize,
                         SOLVE_SMEM);

    head_kernel<<<(HID + 255) / 256, 256>>>(W2, b2, w_deep);
    conv_W1h<<<(int)((size_t)DINV * HID / 4 / 256), 256>>>(W1);
    mlp_tc<<<NROWS / 128, 512, SMEM_TOTAL>>>(d1, b1);
    gram_mma<<<GBLOCKS, 256, GRAM_SMEM>>>(structured);
    gram_reduce<<<SSTR * SSTR / 64, 256>>>();
    solve_cg<<<1, 128, SOLVE_SMEM>>>(w_struct);
    final_kernel<<<(NROWS * 32) / 256, 256>>>(structured, out);
}